// round 10
// baseline (speedup 1.0000x reference)
#include <cuda_runtime.h>
#include <cuda_bf16.h>
#include <math.h>

// ---------------------------------------------------------------------------
// MixMultiHeadAttention  (B=8, D=512, H=8, hd=64, L_s=2048, L_ns=64)
//  L = 2112, L_q = 576, L_k = 2112, L_s_out = 512
// ---------------------------------------------------------------------------

#define BATCH 8
#define DM    512
#define NH    8
#define HD    64
#define LNS   64
#define LS    2048
#define LSO   512
#define LTOT  2112     // LS + LNS
#define LQ    576      // LSO + LNS
#define LK    2112     // LS + LNS
#define DIAG  1536     // LK - LQ

// ---------------- scratch (static device globals; no allocations) ----------
// NOTE: these symbols are ONLY referenced from device code. Referencing them
// in host code (e.g. passing g_attn as a kernel argument) yields the host
// shadow symbol, which GB300's ATS coherence silently reads as zeros.
__device__ float g_K[(size_t)BATCH * NH * LK * HD];     // [b][h][k][d]
__device__ float g_V[(size_t)BATCH * NH * LK * HD];
__device__ float g_Q[(size_t)BATCH * NH * LQ * HD];     // [b][h][q][d]
__device__ float g_attn[(size_t)BATCH * LQ * DM];       // [b*LQ][D]

// ---------------------------------------------------------------------------
// SGEMM: C[M,512] = A[M,512] @ W[512,512] + bias
// MODE 0: A rows gathered from x (per-batch offset), output scattered to
//         head-major [b][h][l][hd] layout in g_K/g_V/g_Q (dst selects).
// MODE 1: A = g_attn (device symbol, resolved in device code), plain
//         row-major output to outParam (d_out).
// 128x128 tile, k-tile 8, 256 threads, 8x8 per-thread microtile.
// ---------------------------------------------------------------------------
template <int MODE>
__global__ void __launch_bounds__(256)
sgemm_proj(const float* __restrict__ A, const float* __restrict__ W,
           const float* __restrict__ bias, float* __restrict__ outParam,
           int dst, int rowsPerBatch, int xRowOffset, int LOut)
{
    __shared__ float As[8 * 132];   // [kk][row], padded stride 132
    __shared__ float Bs[8 * 128];   // [kk][col]

    const int tid = threadIdx.x;
    const int tx = tid & 15;
    const int ty = tid >> 4;
    const int rowBlock = blockIdx.y * 128;
    const int colBlock = blockIdx.x * 128;

    float acc[8][8];
#pragma unroll
    for (int i = 0; i < 8; ++i)
#pragma unroll
        for (int j = 0; j < 8; ++j) acc[i][j] = 0.f;

    const int aRow = tid >> 1;
    const int aCol = (tid & 1) * 4;
    const int bRow = tid >> 5;
    const int bCol = (tid & 31) * 4;

    // resolve this thread's A row pointer once (device-side symbol refs only)
    const float* aptr;
    {
        int grow = rowBlock + aRow;
        if (MODE == 0) {
            int bb = grow / rowsPerBatch;
            int l  = grow - bb * rowsPerBatch;
            aptr = A + ((size_t)bb * LTOT + xRowOffset + l) * DM;
        } else {
            aptr = g_attn + (size_t)grow * DM;   // device-code symbol reference
        }
    }

    for (int k0 = 0; k0 < DM; k0 += 8) {
        float4 av = *(const float4*)(aptr + k0 + aCol);
        As[(aCol + 0) * 132 + aRow] = av.x;
        As[(aCol + 1) * 132 + aRow] = av.y;
        As[(aCol + 2) * 132 + aRow] = av.z;
        As[(aCol + 3) * 132 + aRow] = av.w;
        float4 bv = *(const float4*)(W + (size_t)(k0 + bRow) * DM + colBlock + bCol);
        *(float4*)&Bs[bRow * 128 + bCol] = bv;
        __syncthreads();

#pragma unroll
        for (int kk = 0; kk < 8; ++kk) {
            float ar[8], br[8];
            float4 a0 = *(const float4*)&As[kk * 132 + ty * 8];
            float4 a1 = *(const float4*)&As[kk * 132 + ty * 8 + 4];
            float4 b0 = *(const float4*)&Bs[kk * 128 + tx * 8];
            float4 b1 = *(const float4*)&Bs[kk * 128 + tx * 8 + 4];
            ar[0]=a0.x; ar[1]=a0.y; ar[2]=a0.z; ar[3]=a0.w;
            ar[4]=a1.x; ar[5]=a1.y; ar[6]=a1.z; ar[7]=a1.w;
            br[0]=b0.x; br[1]=b0.y; br[2]=b0.z; br[3]=b0.w;
            br[4]=b1.x; br[5]=b1.y; br[6]=b1.z; br[7]=b1.w;
#pragma unroll
            for (int i = 0; i < 8; ++i)
#pragma unroll
                for (int j = 0; j < 8; ++j)
                    acc[i][j] = fmaf(ar[i], br[j], acc[i][j]);
        }
        __syncthreads();
    }

    // epilogue
    float* outp;
    if (MODE == 0) outp = (dst == 0) ? g_K : (dst == 1) ? g_V : g_Q;
    else           outp = outParam;

#pragma unroll
    for (int i = 0; i < 8; ++i) {
        int grow = rowBlock + ty * 8 + i;
#pragma unroll
        for (int j = 0; j < 8; ++j) {
            int gcol = colBlock + tx * 8 + j;
            float v = acc[i][j] + bias[gcol];
            if (MODE == 0) {
                int bb = grow / rowsPerBatch;
                int l  = grow - bb * rowsPerBatch;
                outp[(((size_t)(bb * NH + (gcol >> 6))) * LOut + l) * HD + (gcol & 63)] = v;
            } else {
                outp[(size_t)grow * DM + gcol] = v;
            }
        }
    }
}

// ---------------------------------------------------------------------------
// Per-token (ns) projection: for token n (global row 2048+n, all 8 batches),
// out[b, :] = x[b, 2048+n, :] @ nw[n] + nb[n].  One block = (n, 256-col chunk).
// Memory-bound on nw; weight reads fully coalesced.
// ---------------------------------------------------------------------------
__global__ void __launch_bounds__(256)
ns_proj(const float* __restrict__ x, const float* __restrict__ nw,
        const float* __restrict__ nb, int dst, int LOut, int basePos)
{
    const int n = blockIdx.x;                   // 0..63
    const int o = blockIdx.y * 256 + threadIdx.x;

    __shared__ float xs[BATCH][DM];
    for (int idx = threadIdx.x; idx < BATCH * DM; idx += 256) {
        int bb = idx >> 9, i = idx & 511;
        xs[bb][i] = x[((size_t)bb * LTOT + LS + n) * DM + i];
    }
    __syncthreads();

    float acc[BATCH];
#pragma unroll
    for (int bb = 0; bb < BATCH; ++bb) acc[bb] = 0.f;

    const float* wp = nw + ((size_t)n * DM) * DM + o;
#pragma unroll 4
    for (int i = 0; i < DM; ++i) {
        float w = wp[(size_t)i * DM];
#pragma unroll
        for (int bb = 0; bb < BATCH; ++bb) acc[bb] = fmaf(xs[bb][i], w, acc[bb]);
    }

    float bias = nb[n * DM + o];
    float* outp = (dst == 0) ? g_K : (dst == 1) ? g_V : g_Q;
    const int hh = o >> 6, dd = o & 63;
#pragma unroll
    for (int bb = 0; bb < BATCH; ++bb)
        outp[(((size_t)(bb * NH + hh)) * LOut + basePos + n) * HD + dd] = acc[bb] + bias;
}

// ---------------------------------------------------------------------------
// Flash attention: block = (q-tile of 64, head, batch), 256 threads.
// K/V tiles of 32 keys -> total smem 41.6 KB static (< 48 KB limit).
// Online softmax; causal offset DIAG=1536; key padding mask on first 2048 keys.
// ---------------------------------------------------------------------------
#define QSTR 65
#define SSTR 33
#define KT   32
#define NKT_TOT (LK / KT)   // 66

__global__ void __launch_bounds__(256)
attn_kernel(const int* __restrict__ pad)
{
    __shared__ float Qs[64 * QSTR];
    __shared__ float Ks[KT * QSTR];
    __shared__ float Vs[KT * QSTR];
    __shared__ float Ss[64 * SSTR];
    __shared__ float mrow[64], arow[64], lrow[64];
    __shared__ int   pads[KT];

    const int qt = blockIdx.x, h = blockIdx.y, b = blockIdx.z;
    const int tid = threadIdx.x;
    const int tx = tid & 15, ty = tid >> 4;

    const size_t bh = (size_t)(b * NH + h);
    const float* Qg = g_Q + (bh * LQ + qt * 64) * HD;
    const float* Kg = g_K + bh * LK * HD;
    const float* Vg = g_V + bh * LK * HD;

    // load Q tile (64 x 64)
    for (int q4 = tid; q4 < 1024; q4 += 256) {
        int r = q4 >> 4, c = (q4 & 15) * 4;
        float4 v = *(const float4*)(Qg + r * 64 + c);
        Qs[r * QSTR + c]     = v.x;
        Qs[r * QSTR + c + 1] = v.y;
        Qs[r * QSTR + c + 2] = v.z;
        Qs[r * QSTR + c + 3] = v.w;
    }
    if (tid < 64) { mrow[tid] = -3.0e38f; lrow[tid] = 0.f; }

    float oacc[16];
#pragma unroll
    for (int i = 0; i < 16; ++i) oacc[i] = 0.f;

    // causal bound in 32-key tiles: keys needed up to qt*64+63+1536
    const int nkt = min(NKT_TOT, 2 * qt + 50);
    __syncthreads();

    for (int kt = 0; kt < nkt; ++kt) {
        const int k0 = kt * KT;
        // load K and V tiles (32 x 64 each)
        for (int q4 = tid; q4 < 512; q4 += 256) {
            int r = q4 >> 4, c = (q4 & 15) * 4;
            float4 kv = *(const float4*)(Kg + (size_t)(k0 + r) * 64 + c);
            Ks[r * QSTR + c]     = kv.x;
            Ks[r * QSTR + c + 1] = kv.y;
            Ks[r * QSTR + c + 2] = kv.z;
            Ks[r * QSTR + c + 3] = kv.w;
            float4 vv = *(const float4*)(Vg + (size_t)(k0 + r) * 64 + c);
            Vs[r * QSTR + c]     = vv.x;
            Vs[r * QSTR + c + 1] = vv.y;
            Vs[r * QSTR + c + 2] = vv.z;
            Vs[r * QSTR + c + 3] = vv.w;
        }
        if (tid < KT) pads[tid] = (k0 >= LS) ? 1 : pad[b * LS + k0 + tid];
        __syncthreads();

        // S = Q @ K^T : 4 q-rows x 2 k-cols per thread
        float s[4][2];
#pragma unroll
        for (int i = 0; i < 4; ++i) { s[i][0] = 0.f; s[i][1] = 0.f; }

#pragma unroll 8
        for (int d = 0; d < 64; ++d) {
            float qv[4], kv[2];
#pragma unroll
            for (int i = 0; i < 4; ++i) qv[i] = Qs[(ty * 4 + i) * QSTR + d];
            kv[0] = Ks[(tx * 2) * QSTR + d];
            kv[1] = Ks[(tx * 2 + 1) * QSTR + d];
#pragma unroll
            for (int i = 0; i < 4; ++i) {
                s[i][0] = fmaf(qv[i], kv[0], s[i][0]);
                s[i][1] = fmaf(qv[i], kv[1], s[i][1]);
            }
        }

        // mask + scale, store to Ss
#pragma unroll
        for (int i = 0; i < 4; ++i) {
            int qg = qt * 64 + ty * 4 + i;
#pragma unroll
            for (int j = 0; j < 2; ++j) {
                int jg = k0 + tx * 2 + j;
                bool valid = (jg <= qg + DIAG) && (pads[tx * 2 + j] != 0);
                Ss[(ty * 4 + i) * SSTR + tx * 2 + j] = valid ? s[i][j] * 0.125f : -1e9f;
            }
        }
        __syncthreads();

        // row max + alpha
        if (tid < 64) {
            float mo = mrow[tid], mn = mo;
#pragma unroll 8
            for (int c = 0; c < KT; ++c) mn = fmaxf(mn, Ss[tid * SSTR + c]);
            mrow[tid] = mn;
            arow[tid] = __expf(mo - mn);
        }
        __syncthreads();

        // exp in place + rescale O accumulators (alpha applied once per tile)
#pragma unroll
        for (int i = 0; i < 4; ++i) {
            int r = ty * 4 + i;
            float mn = mrow[r], al = arow[r];
#pragma unroll
            for (int j = 0; j < 2; ++j) {
                int idx = r * SSTR + tx * 2 + j;
                Ss[idx] = __expf(Ss[idx] - mn);
            }
#pragma unroll
            for (int j = 0; j < 4; ++j) oacc[i * 4 + j] *= al;
        }
        __syncthreads();

        // row sum
        if (tid < 64) {
            float ssum = 0.f;
#pragma unroll 8
            for (int c = 0; c < KT; ++c) ssum += Ss[tid * SSTR + c];
            lrow[tid] = lrow[tid] * arow[tid] + ssum;
        }

        // O += P @ V : 4 q-rows x 4 v-cols per thread
#pragma unroll 8
        for (int c = 0; c < KT; ++c) {
            float pv[4], vv[4];
#pragma unroll
            for (int i = 0; i < 4; ++i) pv[i] = Ss[(ty * 4 + i) * SSTR + c];
#pragma unroll
            for (int j = 0; j < 4; ++j) vv[j] = Vs[c * QSTR + tx * 4 + j];
#pragma unroll
            for (int i = 0; i < 4; ++i)
#pragma unroll
                for (int j = 0; j < 4; ++j)
                    oacc[i * 4 + j] = fmaf(pv[i], vv[j], oacc[i * 4 + j]);
        }
        __syncthreads();
    }

    // write normalized O to g_attn [b*LQ + q][h*64 + col]
#pragma unroll
    for (int i = 0; i < 4; ++i) {
        int qg = qt * 64 + ty * 4 + i;
        float inv = 1.f / lrow[ty * 4 + i];
#pragma unroll
        for (int j = 0; j < 4; ++j)
            g_attn[((size_t)b * LQ + qg) * DM + h * HD + tx * 4 + j] = oacc[i * 4 + j] * inv;
    }
}

// ---------------------------------------------------------------------------
extern "C" void kernel_launch(void* const* d_in, const int* in_sizes, int n_in,
                              void* d_out, int out_size)
{
    const float* x       = (const float*)d_in[0];
    const int*   padmask = (const int*)d_in[1];

    // Robust weight-base detection: L_s / L_s_out may or may not be passed as
    // device scalars (size-1 entries). Skip any size-1 inputs after index 1.
    int base = 2;
    while (base < n_in && in_sizes[base] <= 1) ++base;

    const float* wq_sw = (const float*)d_in[base + 0];
    const float* wq_sb = (const float*)d_in[base + 1];
    const float* wq_nw = (const float*)d_in[base + 2];
    const float* wq_nb = (const float*)d_in[base + 3];
    const float* wk_sw = (const float*)d_in[base + 4];
    const float* wk_sb = (const float*)d_in[base + 5];
    const float* wk_nw = (const float*)d_in[base + 6];
    const float* wk_nb = (const float*)d_in[base + 7];
    const float* wv_sw = (const float*)d_in[base + 8];
    const float* wv_sb = (const float*)d_in[base + 9];
    const float* wv_nw = (const float*)d_in[base + 10];
    const float* wv_nb = (const float*)d_in[base + 11];
    const float* out_w = (const float*)d_in[base + 12];
    const float* out_b = (const float*)d_in[base + 13];
    float* out = (float*)d_out;

    dim3 thr(256);

    // shared-weight projections
    sgemm_proj<0><<<dim3(4, 128), thr>>>(x, wk_sw, wk_sb, nullptr, 0, LS,  0,    LK);
    sgemm_proj<0><<<dim3(4, 128), thr>>>(x, wv_sw, wv_sb, nullptr, 1, LS,  0,    LK);
    sgemm_proj<0><<<dim3(4, 32),  thr>>>(x, wq_sw, wq_sb, nullptr, 2, LSO, 1536, LQ);

    // per-token projections (memory-bound on nw)
    ns_proj<<<dim3(64, 2), thr>>>(x, wk_nw, wk_nb, 0, LK, LS);
    ns_proj<<<dim3(64, 2), thr>>>(x, wv_nw, wv_nb, 1, LK, LS);
    ns_proj<<<dim3(64, 2), thr>>>(x, wq_nw, wq_nb, 2, LQ, LSO);

    // attention (static smem only, < 48 KB: no attribute opt-in required)
    attn_kernel<<<dim3(9, NH, BATCH), thr>>>(padmask);

    // output projection: A = g_attn resolved INSIDE device code (host-side
    // reference to a __device__ symbol is the ATS-readable zero shadow — the
    // exact bug that produced rel_err == 1.0 in R2/R6).
    sgemm_proj<1><<<dim3(4, 36), thr>>>(nullptr, out_w, out_b, out, 3, LQ, 0, 0);
}

// round 11
// speedup vs baseline: 1.8004x; 1.8004x over previous
#include <cuda_runtime.h>
#include <cuda_bf16.h>
#include <math.h>

// ---------------------------------------------------------------------------
// MixMultiHeadAttention  (B=8, D=512, H=8, hd=64, L_s=2048, L_ns=64)
//  L = 2112, L_q = 576, L_k = 2112, L_s_out = 512
// ---------------------------------------------------------------------------

#define BATCH 8
#define DM    512
#define NH    8
#define HD    64
#define LNS   64
#define LS    2048
#define LSO   512
#define LTOT  2112     // LS + LNS
#define LQ    576      // LSO + LNS
#define LK    2112     // LS + LNS
#define DIAG  1536     // LK - LQ

// ---------------- scratch (static device globals; no allocations) ----------
// NOTE: these symbols are ONLY referenced from device code. Referencing them
// in host code (e.g. passing g_attn as a kernel argument) yields the host
// shadow symbol, which GB300's ATS coherence silently reads as zeros
// (confirmed root cause of R2/R6 rel_err == 1.0).
__device__ float g_K[(size_t)BATCH * NH * LK * HD];     // [b][h][k][d]
__device__ float g_V[(size_t)BATCH * NH * LK * HD];
__device__ float g_Q[(size_t)BATCH * NH * LQ * HD];     // [b][h][q][d]
__device__ float g_attn[(size_t)BATCH * LQ * DM];       // [b*LQ][D]

// ---------------------------------------------------------------------------
// SGEMM: C[M,512] = A[M,512] @ W[512,512] + bias  (unchanged from passing R10)
// ---------------------------------------------------------------------------
template <int MODE>
__global__ void __launch_bounds__(256)
sgemm_proj(const float* __restrict__ A, const float* __restrict__ W,
           const float* __restrict__ bias, float* __restrict__ outParam,
           int dst, int rowsPerBatch, int xRowOffset, int LOut)
{
    __shared__ float As[8 * 132];   // [kk][row], padded stride 132
    __shared__ float Bs[8 * 128];   // [kk][col]

    const int tid = threadIdx.x;
    const int tx = tid & 15;
    const int ty = tid >> 4;
    const int rowBlock = blockIdx.y * 128;
    const int colBlock = blockIdx.x * 128;

    float acc[8][8];
#pragma unroll
    for (int i = 0; i < 8; ++i)
#pragma unroll
        for (int j = 0; j < 8; ++j) acc[i][j] = 0.f;

    const int aRow = tid >> 1;
    const int aCol = (tid & 1) * 4;
    const int bRow = tid >> 5;
    const int bCol = (tid & 31) * 4;

    const float* aptr;
    {
        int grow = rowBlock + aRow;
        if (MODE == 0) {
            int bb = grow / rowsPerBatch;
            int l  = grow - bb * rowsPerBatch;
            aptr = A + ((size_t)bb * LTOT + xRowOffset + l) * DM;
        } else {
            aptr = g_attn + (size_t)grow * DM;   // device-code symbol reference
        }
    }

    for (int k0 = 0; k0 < DM; k0 += 8) {
        float4 av = *(const float4*)(aptr + k0 + aCol);
        As[(aCol + 0) * 132 + aRow] = av.x;
        As[(aCol + 1) * 132 + aRow] = av.y;
        As[(aCol + 2) * 132 + aRow] = av.z;
        As[(aCol + 3) * 132 + aRow] = av.w;
        float4 bv = *(const float4*)(W + (size_t)(k0 + bRow) * DM + colBlock + bCol);
        *(float4*)&Bs[bRow * 128 + bCol] = bv;
        __syncthreads();

#pragma unroll
        for (int kk = 0; kk < 8; ++kk) {
            float ar[8], br[8];
            float4 a0 = *(const float4*)&As[kk * 132 + ty * 8];
            float4 a1 = *(const float4*)&As[kk * 132 + ty * 8 + 4];
            float4 b0 = *(const float4*)&Bs[kk * 128 + tx * 8];
            float4 b1 = *(const float4*)&Bs[kk * 128 + tx * 8 + 4];
            ar[0]=a0.x; ar[1]=a0.y; ar[2]=a0.z; ar[3]=a0.w;
            ar[4]=a1.x; ar[5]=a1.y; ar[6]=a1.z; ar[7]=a1.w;
            br[0]=b0.x; br[1]=b0.y; br[2]=b0.z; br[3]=b0.w;
            br[4]=b1.x; br[5]=b1.y; br[6]=b1.z; br[7]=b1.w;
#pragma unroll
            for (int i = 0; i < 8; ++i)
#pragma unroll
                for (int j = 0; j < 8; ++j)
                    acc[i][j] = fmaf(ar[i], br[j], acc[i][j]);
        }
        __syncthreads();
    }

    float* outp;
    if (MODE == 0) outp = (dst == 0) ? g_K : (dst == 1) ? g_V : g_Q;
    else           outp = outParam;

#pragma unroll
    for (int i = 0; i < 8; ++i) {
        int grow = rowBlock + ty * 8 + i;
#pragma unroll
        for (int j = 0; j < 8; ++j) {
            int gcol = colBlock + tx * 8 + j;
            float v = acc[i][j] + bias[gcol];
            if (MODE == 0) {
                int bb = grow / rowsPerBatch;
                int l  = grow - bb * rowsPerBatch;
                outp[(((size_t)(bb * NH + (gcol >> 6))) * LOut + l) * HD + (gcol & 63)] = v;
            } else {
                outp[(size_t)grow * DM + gcol] = v;
            }
        }
    }
}

// ---------------------------------------------------------------------------
// Per-token (ns) projection, v2 — k-split for occupancy + MLP.
// Block = (token n, 64-col chunk och, sel). 256 threads = 64 cols x 4 k-parts.
// Each thread: 128 strided weight loads (unroll 8 -> MLP ~8), 8 batch FMAs per
// load; partials reduced through smem. Grid 64x8x{1,2}: 512/1024 blocks
// (vs 128 before) -> every SM busy; weight stream should approach LTS cap.
// ---------------------------------------------------------------------------
__global__ void __launch_bounds__(256)
ns_proj2(const float* __restrict__ x,
         const float* __restrict__ nw0, const float* __restrict__ nb0,
         const float* __restrict__ nw1, const float* __restrict__ nb1,
         int dst0, int dst1, int LOut, int basePos)
{
    const int n   = blockIdx.x;          // token 0..63
    const int och = blockIdx.y;          // 64-col chunk 0..7 (== head index)
    const int sel = blockIdx.z;          // 0/1 selects weight set (K/V fused)

    const float* nw = sel ? nw1 : nw0;
    const float* nb = sel ? nb1 : nb0;
    const int    dst = sel ? dst1 : dst0;

    __shared__ float xs[BATCH][DM];          // 16 KB: x rows for token n
    __shared__ float part[4][64][9];         // 9 KB: k-part partial sums (padded)

    const int tid = threadIdx.x;

    // cooperative x load: 8 rows x 128 float4 = 1024 float4, 4 per thread
    for (int idx = tid; idx < BATCH * (DM / 4); idx += 256) {
        int bb = idx >> 7, i4 = idx & 127;
        float4 v = *(const float4*)(x + ((size_t)bb * LTOT + LS + n) * DM + i4 * 4);
        *(float4*)&xs[bb][i4 * 4] = v;
    }
    __syncthreads();

    const int oc = tid & 63;                 // col within chunk
    const int kp = tid >> 6;                 // k partition 0..3
    const int o  = och * 64 + oc;            // global output col
    const int i0 = kp * 128;

    float acc[BATCH];
#pragma unroll
    for (int b = 0; b < BATCH; ++b) acc[b] = 0.f;

    const float* wp = nw + (size_t)n * DM * DM + o;
#pragma unroll 8
    for (int i = 0; i < 128; ++i) {
        float w = wp[(size_t)(i0 + i) * DM];    // warp: 128B coalesced line
#pragma unroll
        for (int b = 0; b < BATCH; ++b) acc[b] = fmaf(xs[b][i0 + i], w, acc[b]);
    }

#pragma unroll
    for (int b = 0; b < BATCH; ++b) part[kp][oc][b] = acc[b];
    __syncthreads();

    // reduce 4 partials and scatter: 64 cols x 8 batches = 512 outputs
    float* outp = (dst == 0) ? g_K : (dst == 1) ? g_V : g_Q;
    for (int e = tid; e < 512; e += 256) {
        int ol = e >> 3, b = e & 7;
        float v = part[0][ol][b] + part[1][ol][b] + part[2][ol][b] + part[3][ol][b]
                + nb[n * DM + och * 64 + ol];
        // head index == och (chunks are 64-aligned), lane within head == ol
        outp[(((size_t)(b * NH + och)) * LOut + basePos + n) * HD + ol] = v;
    }
}

// ---------------------------------------------------------------------------
// Flash attention (unchanged from passing R10).
// ---------------------------------------------------------------------------
#define QSTR 65
#define SSTR 33
#define KT   32
#define NKT_TOT (LK / KT)   // 66

__global__ void __launch_bounds__(256)
attn_kernel(const int* __restrict__ pad)
{
    __shared__ float Qs[64 * QSTR];
    __shared__ float Ks[KT * QSTR];
    __shared__ float Vs[KT * QSTR];
    __shared__ float Ss[64 * SSTR];
    __shared__ float mrow[64], arow[64], lrow[64];
    __shared__ int   pads[KT];

    const int qt = blockIdx.x, h = blockIdx.y, b = blockIdx.z;
    const int tid = threadIdx.x;
    const int tx = tid & 15, ty = tid >> 4;

    const size_t bh = (size_t)(b * NH + h);
    const float* Qg = g_Q + (bh * LQ + qt * 64) * HD;
    const float* Kg = g_K + bh * LK * HD;
    const float* Vg = g_V + bh * LK * HD;

    for (int q4 = tid; q4 < 1024; q4 += 256) {
        int r = q4 >> 4, c = (q4 & 15) * 4;
        float4 v = *(const float4*)(Qg + r * 64 + c);
        Qs[r * QSTR + c]     = v.x;
        Qs[r * QSTR + c + 1] = v.y;
        Qs[r * QSTR + c + 2] = v.z;
        Qs[r * QSTR + c + 3] = v.w;
    }
    if (tid < 64) { mrow[tid] = -3.0e38f; lrow[tid] = 0.f; }

    float oacc[16];
#pragma unroll
    for (int i = 0; i < 16; ++i) oacc[i] = 0.f;

    const int nkt = min(NKT_TOT, 2 * qt + 50);
    __syncthreads();

    for (int kt = 0; kt < nkt; ++kt) {
        const int k0 = kt * KT;
        for (int q4 = tid; q4 < 512; q4 += 256) {
            int r = q4 >> 4, c = (q4 & 15) * 4;
            float4 kv = *(const float4*)(Kg + (size_t)(k0 + r) * 64 + c);
            Ks[r * QSTR + c]     = kv.x;
            Ks[r * QSTR + c + 1] = kv.y;
            Ks[r * QSTR + c + 2] = kv.z;
            Ks[r * QSTR + c + 3] = kv.w;
            float4 vv = *(const float4*)(Vg + (size_t)(k0 + r) * 64 + c);
            Vs[r * QSTR + c]     = vv.x;
            Vs[r * QSTR + c + 1] = vv.y;
            Vs[r * QSTR + c + 2] = vv.z;
            Vs[r * QSTR + c + 3] = vv.w;
        }
        if (tid < KT) pads[tid] = (k0 >= LS) ? 1 : pad[b * LS + k0 + tid];
        __syncthreads();

        float s[4][2];
#pragma unroll
        for (int i = 0; i < 4; ++i) { s[i][0] = 0.f; s[i][1] = 0.f; }

#pragma unroll 8
        for (int d = 0; d < 64; ++d) {
            float qv[4], kv[2];
#pragma unroll
            for (int i = 0; i < 4; ++i) qv[i] = Qs[(ty * 4 + i) * QSTR + d];
            kv[0] = Ks[(tx * 2) * QSTR + d];
            kv[1] = Ks[(tx * 2 + 1) * QSTR + d];
#pragma unroll
            for (int i = 0; i < 4; ++i) {
                s[i][0] = fmaf(qv[i], kv[0], s[i][0]);
                s[i][1] = fmaf(qv[i], kv[1], s[i][1]);
            }
        }

#pragma unroll
        for (int i = 0; i < 4; ++i) {
            int qg = qt * 64 + ty * 4 + i;
#pragma unroll
            for (int j = 0; j < 2; ++j) {
                int jg = k0 + tx * 2 + j;
                bool valid = (jg <= qg + DIAG) && (pads[tx * 2 + j] != 0);
                Ss[(ty * 4 + i) * SSTR + tx * 2 + j] = valid ? s[i][j] * 0.125f : -1e9f;
            }
        }
        __syncthreads();

        if (tid < 64) {
            float mo = mrow[tid], mn = mo;
#pragma unroll 8
            for (int c = 0; c < KT; ++c) mn = fmaxf(mn, Ss[tid * SSTR + c]);
            mrow[tid] = mn;
            arow[tid] = __expf(mo - mn);
        }
        __syncthreads();

#pragma unroll
        for (int i = 0; i < 4; ++i) {
            int r = ty * 4 + i;
            float mn = mrow[r], al = arow[r];
#pragma unroll
            for (int j = 0; j < 2; ++j) {
                int idx = r * SSTR + tx * 2 + j;
                Ss[idx] = __expf(Ss[idx] - mn);
            }
#pragma unroll
            for (int j = 0; j < 4; ++j) oacc[i * 4 + j] *= al;
        }
        __syncthreads();

        if (tid < 64) {
            float ssum = 0.f;
#pragma unroll 8
            for (int c = 0; c < KT; ++c) ssum += Ss[tid * SSTR + c];
            lrow[tid] = lrow[tid] * arow[tid] + ssum;
        }

#pragma unroll 8
        for (int c = 0; c < KT; ++c) {
            float pv[4], vv[4];
#pragma unroll
            for (int i = 0; i < 4; ++i) pv[i] = Ss[(ty * 4 + i) * SSTR + c];
#pragma unroll
            for (int j = 0; j < 4; ++j) vv[j] = Vs[c * QSTR + tx * 4 + j];
#pragma unroll
            for (int i = 0; i < 4; ++i)
#pragma unroll
                for (int j = 0; j < 4; ++j)
                    oacc[i * 4 + j] = fmaf(pv[i], vv[j], oacc[i * 4 + j]);
        }
        __syncthreads();
    }

#pragma unroll
    for (int i = 0; i < 4; ++i) {
        int qg = qt * 64 + ty * 4 + i;
        float inv = 1.f / lrow[ty * 4 + i];
#pragma unroll
        for (int j = 0; j < 4; ++j)
            g_attn[((size_t)b * LQ + qg) * DM + h * HD + tx * 4 + j] = oacc[i * 4 + j] * inv;
    }
}

// ---------------------------------------------------------------------------
extern "C" void kernel_launch(void* const* d_in, const int* in_sizes, int n_in,
                              void* d_out, int out_size)
{
    const float* x       = (const float*)d_in[0];
    const int*   padmask = (const int*)d_in[1];

    int base = 2;
    while (base < n_in && in_sizes[base] <= 1) ++base;

    const float* wq_sw = (const float*)d_in[base + 0];
    const float* wq_sb = (const float*)d_in[base + 1];
    const float* wq_nw = (const float*)d_in[base + 2];
    const float* wq_nb = (const float*)d_in[base + 3];
    const float* wk_sw = (const float*)d_in[base + 4];
    const float* wk_sb = (const float*)d_in[base + 5];
    const float* wk_nw = (const float*)d_in[base + 6];
    const float* wk_nb = (const float*)d_in[base + 7];
    const float* wv_sw = (const float*)d_in[base + 8];
    const float* wv_sb = (const float*)d_in[base + 9];
    const float* wv_nw = (const float*)d_in[base + 10];
    const float* wv_nb = (const float*)d_in[base + 11];
    const float* out_w = (const float*)d_in[base + 12];
    const float* out_b = (const float*)d_in[base + 13];
    float* out = (float*)d_out;

    dim3 thr(256);

    // Launch order keeps attn_kernel at index 5 so ncu (-s 5 -c 1) profiles
    // it next round.
    sgemm_proj<0><<<dim3(4, 128), thr>>>(x, wk_sw, wk_sb, nullptr, 0, LS,  0,    LK);   // 0
    sgemm_proj<0><<<dim3(4, 128), thr>>>(x, wv_sw, wv_sb, nullptr, 1, LS,  0,    LK);   // 1
    sgemm_proj<0><<<dim3(4, 32),  thr>>>(x, wq_sw, wq_sb, nullptr, 2, LSO, 1536, LQ);   // 2

    // per-token projections: K+V fused (z=2), Q separate
    ns_proj2<<<dim3(64, 8, 2), thr>>>(x, wk_nw, wk_nb, wv_nw, wv_nb, 0, 1, LK, LS);     // 3
    ns_proj2<<<dim3(64, 8, 1), thr>>>(x, wq_nw, wq_nb, wq_nw, wq_nb, 2, 2, LQ, LSO);    // 4

    attn_kernel<<<dim3(9, NH, BATCH), thr>>>(padmask);                                   // 5

    sgemm_proj<1><<<dim3(4, 36), thr>>>(nullptr, out_w, out_b, out, 3, LQ, 0, 0);        // 6
}